// round 10
// baseline (speedup 1.0000x reference)
#include <cuda_runtime.h>
#include <cstdint>

// KVGather: out[n,i,k,w,c] = r_weight[n,i,k] * kv[n, r_idx[n,i,k], w, c]
// N=16, P2=64, TOPK=8, W2=64, C_KV=512
// At the compulsory traffic floor (1.074 GiB write + ~75 MB read spill),
// DRAM-bound at 83.6% (R8). R10: one full 128 KB tile per block (4x fewer
// blocks) to amortize the index probe/load/setup; memory instruction mix is
// exactly the proven R8 path (128-bit nc loads + L2 evict_last hint,
// __stcs evict-first streaming stores).

#define KVG_N     16
#define KVG_P2    64
#define KVG_TOPK  8
#define KVG_W2    64
#define KVG_CKV   512

#define NUM_TILES   (KVG_N * KVG_P2 * KVG_TOPK)      // 8192
#define TILE_F4     (KVG_W2 * KVG_CKV / 4)           // 8192 float4 per tile (128 KB)
#define THREADS     256
#define GROUPS      4                                // 4 groups of 8 f4/thread
#define F4_PER_GRP  8
#define GRID        NUM_TILES                        // 8192 blocks, 1 tile each

__device__ __forceinline__ float4 ldg_l2el(const float4* p, uint64_t pol) {
    float4 v;
    asm("ld.global.nc.L2::cache_hint.v4.f32 {%0,%1,%2,%3}, [%4], %5;"
        : "=f"(v.x), "=f"(v.y), "=f"(v.z), "=f"(v.w)
        : "l"(p), "l"(pol));
    return v;
}

__global__ __launch_bounds__(THREADS, 8)
void kvg_gather_kernel(const float4* __restrict__ kv,
                       const float*  __restrict__ r_weight,
                       const void*   __restrict__ r_idx,
                       float4*       __restrict__ out) {
    const int tile = blockIdx.x;
    const int n    = tile >> 9;            // / (P2*TOPK)

    // ---- int64-vs-int32 index-width detection, fused in-kernel ----
    // int64 values in [0,64) -> every odd 32-bit word 0; int32 indices ->
    // OR of 32 odd words nonzero w.p. 1-(1/64)^32. Words [1..63] are
    // in-bounds for both layouts; sectors are L2-hot.
    const int lane = threadIdx.x & 31;
    unsigned probe = ((const unsigned*)r_idx)[2 * lane + 1];
    const bool is64 = (__reduce_or_sync(0xffffffffu, probe) == 0u);

    long long idx;
    if (is64) idx = ((const long long*)r_idx)[tile];
    else      idx = (long long)((const int*)r_idx)[tile];

    const float wt = r_weight[tile];

    // L2 evict-last for the hot kv read set (verified +0.8% DRAM in R8).
    uint64_t pol;
    asm("createpolicy.fractional.L2::evict_last.b64 %0, 1.0;" : "=l"(pol));

    const float4* __restrict__ src =
        kv + ((long long)n * KVG_P2 + idx) * (long long)TILE_F4;
    float4* __restrict__ dst = out + (long long)tile * (long long)TILE_F4;

#pragma unroll
    for (int g = 0; g < GROUPS; g++) {
        const int base = g * (F4_PER_GRP * THREADS) + threadIdx.x;

        // Batch 8 loads (deep MLP window), then 8 scaled streaming stores.
        float4 r[F4_PER_GRP];
#pragma unroll
        for (int j = 0; j < F4_PER_GRP; j++)
            r[j] = ldg_l2el(&src[base + j * THREADS], pol);

#pragma unroll
        for (int j = 0; j < F4_PER_GRP; j++) {
            float4 v = r[j];
            v.x *= wt; v.y *= wt; v.z *= wt; v.w *= wt;
            __stcs(&dst[base + j * THREADS], v);
        }
    }
}

extern "C" void kernel_launch(void* const* d_in, const int* in_sizes, int n_in,
                              void* d_out, int out_size) {
    // metadata order: r_idx, r_weight, kv
    const void*  r_idx    = d_in[0];
    const float* r_weight = (const float*)d_in[1];
    const float4* kv      = (const float4*)d_in[2];
    float4* out           = (float4*)d_out;

    kvg_gather_kernel<<<GRID, THREADS>>>(kv, r_weight, r_idx, out);
}

// round 11
// speedup vs baseline: 1.0647x; 1.0647x over previous
#include <cuda_runtime.h>
#include <cstdint>

// KVGather: out[n,i,k,w,c] = r_weight[n,i,k] * kv[n, r_idx[n,i,k], w, c]
// N=16, P2=64, TOPK=8, W2=64, C_KV=512
// At the compulsory traffic floor; DRAM-bound (best: R8, 173.2us, 83.6%).
// Evidence across R6/R10: many small one-shot blocks beat coarsened blocks.
// R11 single variable: halve block size (128 thr, 1024-f4 chunk, 65536
// blocks), keeping the exact R8 per-warp memory instruction mix.

#define KVG_N     16
#define KVG_P2    64
#define KVG_TOPK  8
#define KVG_W2    64
#define KVG_CKV   512

#define NUM_TILES   (KVG_N * KVG_P2 * KVG_TOPK)      // 8192
#define TILE_F4     (KVG_W2 * KVG_CKV / 4)           // 8192 float4 per tile (128 KB)
#define F4_PER_THR  8
#define THREADS     128
#define F4_PER_BLK  (F4_PER_THR * THREADS)           // 1024
#define BLKS_PER_TILE (TILE_F4 / F4_PER_BLK)         // 8
#define GRID        (NUM_TILES * BLKS_PER_TILE)      // 65536

__device__ __forceinline__ float4 ldg_l2el(const float4* p, uint64_t pol) {
    float4 v;
    asm("ld.global.nc.L2::cache_hint.v4.f32 {%0,%1,%2,%3}, [%4], %5;"
        : "=f"(v.x), "=f"(v.y), "=f"(v.z), "=f"(v.w)
        : "l"(p), "l"(pol));
    return v;
}

__global__ __launch_bounds__(THREADS, 16)
void kvg_gather_kernel(const float4* __restrict__ kv,
                       const float*  __restrict__ r_weight,
                       const void*   __restrict__ r_idx,
                       float4*       __restrict__ out) {
    const int bid   = blockIdx.x;
    const int tile  = bid >> 3;            // BLKS_PER_TILE = 8
    const int chunk = bid & 7;
    const int n     = tile >> 9;           // / (P2*TOPK)

    // ---- int64-vs-int32 index-width detection, fused in-kernel ----
    // int64 values in [0,64) -> every odd 32-bit word 0; int32 indices ->
    // OR of 32 odd words nonzero w.p. 1-(1/64)^32. Words [1..63] are
    // in-bounds for both layouts; sectors are L2-hot.
    const int lane = threadIdx.x & 31;
    unsigned probe = ((const unsigned*)r_idx)[2 * lane + 1];
    unsigned odd_or = __reduce_or_sync(0xffffffffu, probe);
    const bool is64 = (odd_or == 0u);

    long long idx;
    if (is64) idx = ((const long long*)r_idx)[tile];
    else      idx = (long long)((const int*)r_idx)[tile];

    const float wt = r_weight[tile];

    // L2 evict-last for the hot kv read set (verified +0.8% DRAM in R8).
    uint64_t pol;
    asm("createpolicy.fractional.L2::evict_last.b64 %0, 1.0;" : "=l"(pol));

    const float4* __restrict__ src =
        kv + ((long long)n * KVG_P2 + idx) * (long long)TILE_F4;
    float4* __restrict__ dst = out + (long long)tile * (long long)TILE_F4;

    const int base = chunk * F4_PER_BLK + threadIdx.x;

#pragma unroll
    for (int j = 0; j < F4_PER_THR; j++) {
        const int p = base + j * THREADS;
        float4 v = ldg_l2el(&src[p], pol);
        v.x *= wt; v.y *= wt; v.z *= wt; v.w *= wt;
        // Streaming store: evict-first write stream (proven R7 A/B).
        __stcs(&dst[p], v);
    }
}

extern "C" void kernel_launch(void* const* d_in, const int* in_sizes, int n_in,
                              void* d_out, int out_size) {
    // metadata order: r_idx, r_weight, kv
    const void*  r_idx    = d_in[0];
    const float* r_weight = (const float*)d_in[1];
    const float4* kv      = (const float4*)d_in[2];
    float4* out           = (float4*)d_out;

    kvg_gather_kernel<<<GRID, THREADS>>>(kv, r_weight, r_idx, out);
}